// round 14
// baseline (speedup 1.0000x reference)
#include <cuda_runtime.h>
#include <cuda_fp16.h>
#include <cstdint>

// ---------------------------------------------------------------------------
// Scratch (device globals — no allocations allowed)
// ---------------------------------------------------------------------------
__device__ __half    g_Yh[32 * 56 * 56 * 256];        // NHWC fp16 normalized input
__device__ __half    g_V[16 * 25088 * 256];           // Winograd input transform [r][tile][ic]
__device__ __half    g_U[16 * 256 * 256];             // Winograd weights [r][oc][ic]
__device__ uint32_t  g_M2[16 * 128 * 25088];          // GEMM result, half2 [r][oc/2][tile]

// ---------------------------------------------------------------------------
// Kernel 1: Golay scale + FWHT(256) + RMSNorm -> g_Yh (NHWC, fp16)
// ---------------------------------------------------------------------------
__global__ __launch_bounds__(256) void wht_kernel(const float* __restrict__ x,
                                                  const float* __restrict__ rmsw) {
    __shared__ float s[256][33];
    const int p0   = blockIdx.x * 32;
    const int n    = blockIdx.y;
    const int t    = threadIdx.x;
    const int lane = t & 31;
    const int warp = t >> 5;

    const float* xb = x + (size_t)n * 256 * 3136 + p0 + lane;
#pragma unroll 8
    for (int it = 0; it < 32; ++it) {
        int ch = warp * 32 + it;
        float v = xb[(size_t)ch * 3136];
        float gs = (__popc(ch & (ch >> 1)) & 1) ? -1.0f : 1.0f;  // Rudin-Shapiro
        s[ch][lane] = v * gs;
    }
    __syncthreads();

    __half* Yb = g_Yh + ((size_t)(n * 3136 + p0)) * 256;

    for (int j = 0; j < 4; ++j) {
        int pl = warp * 4 + j;
        float v[8];
#pragma unroll
        for (int i = 0; i < 8; ++i) v[i] = s[i * 32 + lane][pl];
#pragma unroll
        for (int b = 0; b < 3; ++b) {
            int m = 1 << b;
#pragma unroll
            for (int i = 0; i < 8; ++i)
                if (!(i & m)) {
                    float lo = v[i], hi = v[i | m];
                    v[i] = lo + hi;
                    v[i | m] = lo - hi;
                }
        }
#pragma unroll
        for (int b = 0; b < 5; ++b) {
            int m = 1 << b;
#pragma unroll
            for (int i = 0; i < 8; ++i) {
                float o = __shfl_xor_sync(0xffffffffu, v[i], m);
                v[i] = (lane & m) ? (o - v[i]) : (v[i] + o);
            }
        }
        float ss = 0.0f;
#pragma unroll
        for (int i = 0; i < 8; ++i) ss += v[i] * v[i];
#pragma unroll
        for (int off = 16; off; off >>= 1) ss += __shfl_xor_sync(0xffffffffu, ss, off);
        float sc = rsqrtf(ss * (1.0f / 256.0f) + 1e-5f);
#pragma unroll
        for (int i = 0; i < 8; ++i) {
            float val = v[i] * sc * rmsw[i * 32 + lane];
            Yb[(size_t)pl * 256 + i * 32 + lane] = __float2half_rn(val);
        }
    }
}

// ---------------------------------------------------------------------------
// Kernel 2: Winograd input transform  V = B^T d B  (fp32 math, fp16 store)
// ---------------------------------------------------------------------------
__global__ __launch_bounds__(256) void wino_in(void) {
    const int t  = threadIdx.x;
    const int tg = t >> 6;
    const int lt = t & 63;
    const int T  = blockIdx.x * 4 + tg;
    const int n   = T / 784;
    const int rem = T - n * 784;
    const int ty  = rem / 28;
    const int tx  = rem - ty * 28;

    uint2 dly[16];
#pragma unroll
    for (int dy = 0; dy < 4; ++dy)
#pragma unroll
        for (int dx = 0; dx < 4; ++dx) {
            int py = 2 * ty - 1 + dy;
            int px = 2 * tx - 1 + dx;
            bool valid = ((unsigned)py < 56u) && ((unsigned)px < 56u);
            if (valid)
                dly[dy * 4 + dx] = *(const uint2*)(g_Yh +
                    ((size_t)(n * 3136 + py * 56 + px)) * 256 + lt * 4);
            else
                dly[dy * 4 + dx] = make_uint2(0u, 0u);
        }

    __half2 vpack[2][16];
#pragma unroll
    for (int cp = 0; cp < 2; ++cp) {
        float da[16], db[16];
#pragma unroll
        for (int i = 0; i < 16; ++i) {
            uint32_t w = cp ? dly[i].y : dly[i].x;
            __half2 h2 = *(__half2*)&w;
            da[i] = __low2float(h2);
            db[i] = __high2float(h2);
        }
#pragma unroll
        for (int cc = 0; cc < 2; ++cc) {
            float* d = cc ? db : da;
            float tt[16];
#pragma unroll
            for (int xx = 0; xx < 4; ++xx) {
                tt[0 * 4 + xx] = d[0 * 4 + xx] - d[2 * 4 + xx];
                tt[1 * 4 + xx] = d[1 * 4 + xx] + d[2 * 4 + xx];
                tt[2 * 4 + xx] = d[2 * 4 + xx] - d[1 * 4 + xx];
                tt[3 * 4 + xx] = d[1 * 4 + xx] - d[3 * 4 + xx];
            }
            float V[16];
#pragma unroll
            for (int u = 0; u < 4; ++u) {
                V[u * 4 + 0] = tt[u * 4 + 0] - tt[u * 4 + 2];
                V[u * 4 + 1] = tt[u * 4 + 1] + tt[u * 4 + 2];
                V[u * 4 + 2] = tt[u * 4 + 2] - tt[u * 4 + 1];
                V[u * 4 + 3] = tt[u * 4 + 1] - tt[u * 4 + 3];
            }
#pragma unroll
            for (int r = 0; r < 16; ++r) {
                __half hv = __float2half_rn(V[r]);
                if (cc == 0) vpack[cp][r] = __halves2half2(hv, hv);
                else         vpack[cp][r] = __halves2half2(__low2half(vpack[cp][r]), hv);
            }
        }
    }
#pragma unroll
    for (int r = 0; r < 16; ++r) {
        uint2 w;
        w.x = *(uint32_t*)&vpack[0][r];
        w.y = *(uint32_t*)&vpack[1][r];
        *(uint2*)(g_V + ((size_t)r * 25088 + T) * 256 + lt * 4) = w;
    }
}

// ---------------------------------------------------------------------------
// Kernel 3: Winograd weight transform  U = G g G^T  (fp32 math, fp16 store)
// ---------------------------------------------------------------------------
__global__ __launch_bounds__(256) void wino_wt(const float* __restrict__ W) {
    int oc = blockIdx.x;
    int ic = threadIdx.x;
    const float* g = W + ((size_t)oc * 256 + ic) * 9;
    float gg[9];
#pragma unroll
    for (int i = 0; i < 9; ++i) gg[i] = g[i];
    float tt[12];
#pragma unroll
    for (int j = 0; j < 3; ++j) {
        tt[0 * 3 + j] = gg[0 * 3 + j];
        tt[1 * 3 + j] = 0.5f * (gg[0 * 3 + j] + gg[1 * 3 + j] + gg[2 * 3 + j]);
        tt[2 * 3 + j] = 0.5f * (gg[0 * 3 + j] - gg[1 * 3 + j] + gg[2 * 3 + j]);
        tt[3 * 3 + j] = gg[2 * 3 + j];
    }
#pragma unroll
    for (int u = 0; u < 4; ++u) {
        float U0 = tt[u * 3 + 0];
        float U1 = 0.5f * (tt[u * 3 + 0] + tt[u * 3 + 1] + tt[u * 3 + 2]);
        float U2 = 0.5f * (tt[u * 3 + 0] - tt[u * 3 + 1] + tt[u * 3 + 2]);
        float U3 = tt[u * 3 + 2];
        g_U[(size_t)(u * 4 + 0) * 65536 + oc * 256 + ic] = __float2half_rn(U0);
        g_U[(size_t)(u * 4 + 1) * 65536 + oc * 256 + ic] = __float2half_rn(U1);
        g_U[(size_t)(u * 4 + 2) * 65536 + oc * 256 + ic] = __float2half_rn(U2);
        g_U[(size_t)(u * 4 + 3) * 65536 + oc * 256 + ic] = __float2half_rn(U3);
    }
}

// ---------------------------------------------------------------------------
// Kernel 4: GEMMs M_r = V_r * U_r^T -> g_M2, r-loop INSIDE the CTA so the
// cp.async ring never drains. Grid (4 ocb, 196 tb) = 784 CTAs, 64 chunks
// each (q = r*4+kc). CTA tile 128 tiles x 64 oc, 8 warps = 4(m)x2(n),
// warp tile 32x32 = 8 MMA chains, acc 32 regs, reset per r.
// 4-stage ring, 1 sync/chunk, issue-before-compute. 2 CTAs/SM.
// ---------------------------------------------------------------------------
#define GA_BYTES   (128 * 144)               // 18432
#define GB_BYTES   (64 * 144)                // 9216
#define GSTAGE     (GA_BYTES + GB_BYTES)     // 27648
#define GG_SMEM    (4 * GSTAGE)              // 110592 -> 2 CTAs/SM

#define LDSM4(r0, r1, r2, r3, addr)                                            \
    asm volatile("ldmatrix.sync.aligned.m8n8.x4.shared.b16 {%0,%1,%2,%3}, [%4];" \
                 : "=r"(r0), "=r"(r1), "=r"(r2), "=r"(r3) : "r"(addr))

__global__ __launch_bounds__(256, 2) void wino_gemm2(void) {
    extern __shared__ __half sm[];
    const int t      = threadIdx.x;
    const int lane   = t & 31;
    const int warp   = t >> 5;
    const int warp_m = warp >> 1;   // 0..3 -> 32-tile group
    const int warp_n = warp & 1;    // 0..1 -> 32-oc group
    const int g      = lane >> 2;
    const int t4     = lane & 3;

    const int OB = blockIdx.x * 64;     // oc block
    const int TB = blockIdx.y * 128;    // tile block

    uint32_t sbase = (uint32_t)__cvta_generic_to_shared(sm);

    // cp.async geometry: 4 A units + 2 B units per thread
    const int row0 = t >> 3;            // 0..31
    const int u0   = t & 7;

    // ldmatrix lane offsets
    const int arow = (lane & 7) + (((lane >> 3) & 1) << 3);
    const int acol = (lane >> 4) << 3;
    const int brow = (lane & 7) + ((lane >> 4) << 3);
    const int bcol = ((lane >> 3) & 1) << 3;
    uint32_t aoff[2], boff[2];
#pragma unroll
    for (int mt = 0; mt < 2; ++mt)
        aoff[mt] = (uint32_t)(((warp_m * 32 + mt * 16 + arow) * 72 + acol) * 2);
#pragma unroll
    for (int j = 0; j < 2; ++j)
        boff[j] = (uint32_t)(GA_BYTES + ((warp_n * 32 + j * 16 + brow) * 72 + bcol) * 2);

    // Epilogue store geometry (constant): g_M2[r][ocp][T]
    const int ocp0 = (OB >> 1) + warp_n * 16 + t4;       // + nt*4
    const int Tr0  = TB + warp_m * 32 + g;               // + mt*16 (+8 for hi regs)

    float acc[8][4];
#pragma unroll
    for (int e = 0; e < 8; ++e)
#pragma unroll
        for (int k = 0; k < 4; ++k) acc[e][k] = 0.0f;

    auto issue = [&](int q, int st) {
        int r  = q >> 2;
        int kc = q & 3;
        uint32_t abase = sbase + (uint32_t)(st * GSTAGE);
        const __half* Vp = g_V + ((size_t)(r * 25088 + TB)) * 256 + kc * 64 + u0 * 8;
        const __half* Up = g_U + ((size_t)(r * 256 + OB)) * 256 + kc * 64 + u0 * 8;
#pragma unroll
        for (int j = 0; j < 4; ++j) {
            int row = row0 + j * 32;
            uint32_t sa = abase + (uint32_t)(row * 144 + u0 * 16);
            asm volatile("cp.async.cg.shared.global [%0], [%1], 16;\n"
                         :: "r"(sa), "l"(Vp + (size_t)row * 256));
        }
#pragma unroll
        for (int j = 0; j < 2; ++j) {
            int row = row0 + j * 32;
            uint32_t sa = abase + (uint32_t)(GA_BYTES + row * 144 + u0 * 16);
            asm volatile("cp.async.cg.shared.global [%0], [%1], 16;\n"
                         :: "r"(sa), "l"(Up + (size_t)row * 256));
        }
        asm volatile("cp.async.commit_group;\n");
    };

    issue(0, 0);
    issue(1, 1);
    issue(2, 2);

    for (int q = 0; q < 64; ++q) {
        int st = q & 3;
        if (q <= 61)      asm volatile("cp.async.wait_group 2;\n" ::: "memory");
        else if (q == 62) asm volatile("cp.async.wait_group 1;\n" ::: "memory");
        else              asm volatile("cp.async.wait_group 0;\n" ::: "memory");
        __syncthreads();
        if (q + 3 < 64) issue(q + 3, (q + 3) & 3);   // stage (q-1)&3 is free

        uint32_t abase = sbase + (uint32_t)(st * GSTAGE);

        uint32_t a0[8], a1[8], b0[8], b1[8];
        LDSM4(a0[0], a0[1], a0[2], a0[3], abase + aoff[0]);
        LDSM4(a0[4], a0[5], a0[6], a0[7], abase + aoff[1]);
        LDSM4(b0[0], b0[1], b0[2], b0[3], abase + boff[0]);
        LDSM4(b0[4], b0[5], b0[6], b0[7], abase + boff[1]);

#pragma unroll
        for (int ks = 0; ks < 4; ++ks) {
            uint32_t* ac = (ks & 1) ? a1 : a0;
            uint32_t* bc = (ks & 1) ? b1 : b0;
            if (ks < 3) {
                uint32_t* an = (ks & 1) ? a0 : a1;
                uint32_t* bn = (ks & 1) ? b0 : b1;
                uint32_t ko = (uint32_t)((ks + 1) * 32);
                LDSM4(an[0], an[1], an[2], an[3], abase + aoff[0] + ko);
                LDSM4(an[4], an[5], an[6], an[7], abase + aoff[1] + ko);
                LDSM4(bn[0], bn[1], bn[2], bn[3], abase + boff[0] + ko);
                LDSM4(bn[4], bn[5], bn[6], bn[7], abase + boff[1] + ko);
            }
#pragma unroll
            for (int mt = 0; mt < 2; ++mt)
#pragma unroll
                for (int nt = 0; nt < 4; ++nt) {
                    int e  = mt * 4 + nt;
                    int bj = (nt >> 1) * 4 + (nt & 1) * 2;
                    asm volatile(
                        "mma.sync.aligned.m16n8k16.row.col.f32.f16.f16.f32 "
                        "{%0,%1,%2,%3}, {%4,%5,%6,%7}, {%8,%9}, {%0,%1,%2,%3};\n"
                        : "+f"(acc[e][0]), "+f"(acc[e][1]),
                          "+f"(acc[e][2]), "+f"(acc[e][3])
                        : "r"(ac[mt * 4]), "r"(ac[mt * 4 + 1]),
                          "r"(ac[mt * 4 + 2]), "r"(ac[mt * 4 + 3]),
                          "r"(bc[bj]), "r"(bc[bj + 1]));
                }
        }

        if ((q & 3) == 3) {
            // r finished: store acc -> g_M2[r], reset acc. Overlaps next r's ring.
            int r = q >> 2;
#pragma unroll
            for (int mt = 0; mt < 2; ++mt)
#pragma unroll
                for (int nt = 0; nt < 4; ++nt) {
                    int e = mt * 4 + nt;
                    size_t idx = ((size_t)r * 128 + (ocp0 + nt * 4)) * 25088 +
                                 (Tr0 + mt * 16);
                    __half2 h0 = __floats2half2_rn(acc[e][0], acc[e][1]);
                    __half2 h1 = __floats2half2_rn(acc[e][2], acc[e][3]);
                    g_M2[idx]     = *(uint32_t*)&h0;
                    g_M2[idx + 8] = *(uint32_t*)&h1;
                    acc[e][0] = 0.0f; acc[e][1] = 0.0f;
                    acc[e][2] = 0.0f; acc[e][3] = 0.0f;
                }
        }
    }
}

// ---------------------------------------------------------------------------
// Kernel 5: output transform  Y = A^T M A + bias  (streaming).
// A^T = [[1,1,1,0],[0,1,-1,-1]]
// ---------------------------------------------------------------------------
__global__ __launch_bounds__(256) void wino_out(const float* __restrict__ bias,
                                                float* __restrict__ out) {
    const int lane = threadIdx.x & 31;
    const int warp = threadIdx.x >> 5;
    const int ocp  = blockIdx.y * 8 + warp;
    const int T    = blockIdx.x * 32 + lane;

    const int n   = T / 784;
    const int rem = T - n * 784;
    const int ty  = rem / 28;
    const int tx  = rem - ty * 28;

    uint32_t mv[16];
#pragma unroll
    for (int r = 0; r < 16; ++r)
        mv[r] = g_M2[((size_t)r * 128 + ocp) * 25088 + T];

    size_t base0 = (size_t)n * (256 * 3136) + ((size_t)ocp * 2) * 3136 +
                   (2 * ty) * 56 + 2 * tx;

#pragma unroll
    for (int c = 0; c < 2; ++c) {
        float m[16];
#pragma unroll
        for (int r = 0; r < 16; ++r) {
            float2 f = __half22float2(*(__half2*)&mv[r]);
            m[r] = c ? f.y : f.x;
        }
        float rt0[4], rt1[4];
#pragma unroll
        for (int uu = 0; uu < 4; ++uu) {
            rt0[uu] = m[uu * 4 + 0] + m[uu * 4 + 1] + m[uu * 4 + 2];
            rt1[uu] = m[uu * 4 + 1] - m[uu * 4 + 2] - m[uu * 4 + 3];
        }
        float y00 = rt0[0] + rt0[1] + rt0[2];
        float y01 = rt1[0] + rt1[1] + rt1[2];
        float y10 = rt0[1] - rt0[2] - rt0[3];
        float y11 = rt1[1] - rt1[2] - rt1[3];

        float bv = __ldg(bias + ocp * 2 + c);
        float* ob = out + base0 + (size_t)c * 3136;
        *(float2*)(ob)      = make_float2(y00 + bv, y01 + bv);
        *(float2*)(ob + 56) = make_float2(y10 + bv, y11 + bv);
    }
}

// ---------------------------------------------------------------------------
// Launcher (graph-capturable: kernel launches only)
// ---------------------------------------------------------------------------
extern "C" void kernel_launch(void* const* d_in, const int* in_sizes, int n_in,
                              void* d_out, int out_size) {
    const float* x    = (const float*)d_in[0];
    const float* W    = (const float*)d_in[1];
    const float* b    = (const float*)d_in[2];
    const float* rmsw = (const float*)d_in[3];
    float* out = (float*)d_out;

    wht_kernel<<<dim3(98, 32), 256>>>(x, rmsw);
    wino_in<<<6272, 256>>>();
    wino_wt<<<256, 256>>>(W);

    cudaFuncSetAttribute(wino_gemm2, cudaFuncAttributeMaxDynamicSharedMemorySize,
                         GG_SMEM);
    wino_gemm2<<<dim3(4, 196), 256, GG_SMEM>>>();

    wino_out<<<dim3(784, 16), 256>>>(b, out);
}

// round 16
// speedup vs baseline: 1.3257x; 1.3257x over previous
#include <cuda_runtime.h>
#include <cuda_fp16.h>
#include <cstdint>

// ---------------------------------------------------------------------------
// Scratch (device globals — no allocations allowed)
// ---------------------------------------------------------------------------
__device__ __half    g_Yh[32 * 56 * 56 * 256];        // NHWC fp16 normalized input
__device__ __half    g_V[16 * 25088 * 256];           // Winograd input transform [r][tile][ic]
__device__ __half    g_U[16 * 256 * 256];             // Winograd weights [r][oc][ic]
__device__ uint32_t  g_M2[16 * 128 * 25088];          // GEMM result, half2 [r][oc/2][tile]

// ---------------------------------------------------------------------------
// Kernel 1: Golay scale + FWHT(256) + RMSNorm -> g_Yh (NHWC, fp16)
// ---------------------------------------------------------------------------
__global__ __launch_bounds__(256) void wht_kernel(const float* __restrict__ x,
                                                  const float* __restrict__ rmsw) {
    __shared__ float s[256][33];
    const int p0   = blockIdx.x * 32;
    const int n    = blockIdx.y;
    const int t    = threadIdx.x;
    const int lane = t & 31;
    const int warp = t >> 5;

    const float* xb = x + (size_t)n * 256 * 3136 + p0 + lane;
#pragma unroll 8
    for (int it = 0; it < 32; ++it) {
        int ch = warp * 32 + it;
        float v = xb[(size_t)ch * 3136];
        float gs = (__popc(ch & (ch >> 1)) & 1) ? -1.0f : 1.0f;  // Rudin-Shapiro
        s[ch][lane] = v * gs;
    }
    __syncthreads();

    __half* Yb = g_Yh + ((size_t)(n * 3136 + p0)) * 256;

    for (int j = 0; j < 4; ++j) {
        int pl = warp * 4 + j;
        float v[8];
#pragma unroll
        for (int i = 0; i < 8; ++i) v[i] = s[i * 32 + lane][pl];
#pragma unroll
        for (int b = 0; b < 3; ++b) {
            int m = 1 << b;
#pragma unroll
            for (int i = 0; i < 8; ++i)
                if (!(i & m)) {
                    float lo = v[i], hi = v[i | m];
                    v[i] = lo + hi;
                    v[i | m] = lo - hi;
                }
        }
#pragma unroll
        for (int b = 0; b < 5; ++b) {
            int m = 1 << b;
#pragma unroll
            for (int i = 0; i < 8; ++i) {
                float o = __shfl_xor_sync(0xffffffffu, v[i], m);
                v[i] = (lane & m) ? (o - v[i]) : (v[i] + o);
            }
        }
        float ss = 0.0f;
#pragma unroll
        for (int i = 0; i < 8; ++i) ss += v[i] * v[i];
#pragma unroll
        for (int off = 16; off; off >>= 1) ss += __shfl_xor_sync(0xffffffffu, ss, off);
        float sc = rsqrtf(ss * (1.0f / 256.0f) + 1e-5f);
#pragma unroll
        for (int i = 0; i < 8; ++i) {
            float val = v[i] * sc * rmsw[i * 32 + lane];
            Yb[(size_t)pl * 256 + i * 32 + lane] = __float2half_rn(val);
        }
    }
}

// ---------------------------------------------------------------------------
// Kernel 2: Winograd input transform  V = B^T d B  (fp32 math, fp16 store)
// ---------------------------------------------------------------------------
__global__ __launch_bounds__(256) void wino_in(void) {
    const int t  = threadIdx.x;
    const int tg = t >> 6;
    const int lt = t & 63;
    const int T  = blockIdx.x * 4 + tg;
    const int n   = T / 784;
    const int rem = T - n * 784;
    const int ty  = rem / 28;
    const int tx  = rem - ty * 28;

    uint2 dly[16];
#pragma unroll
    for (int dy = 0; dy < 4; ++dy)
#pragma unroll
        for (int dx = 0; dx < 4; ++dx) {
            int py = 2 * ty - 1 + dy;
            int px = 2 * tx - 1 + dx;
            bool valid = ((unsigned)py < 56u) && ((unsigned)px < 56u);
            if (valid)
                dly[dy * 4 + dx] = *(const uint2*)(g_Yh +
                    ((size_t)(n * 3136 + py * 56 + px)) * 256 + lt * 4);
            else
                dly[dy * 4 + dx] = make_uint2(0u, 0u);
        }

    __half2 vpack[2][16];
#pragma unroll
    for (int cp = 0; cp < 2; ++cp) {
        float da[16], db[16];
#pragma unroll
        for (int i = 0; i < 16; ++i) {
            uint32_t w = cp ? dly[i].y : dly[i].x;
            __half2 h2 = *(__half2*)&w;
            da[i] = __low2float(h2);
            db[i] = __high2float(h2);
        }
#pragma unroll
        for (int cc = 0; cc < 2; ++cc) {
            float* d = cc ? db : da;
            float tt[16];
#pragma unroll
            for (int xx = 0; xx < 4; ++xx) {
                tt[0 * 4 + xx] = d[0 * 4 + xx] - d[2 * 4 + xx];
                tt[1 * 4 + xx] = d[1 * 4 + xx] + d[2 * 4 + xx];
                tt[2 * 4 + xx] = d[2 * 4 + xx] - d[1 * 4 + xx];
                tt[3 * 4 + xx] = d[1 * 4 + xx] - d[3 * 4 + xx];
            }
            float V[16];
#pragma unroll
            for (int u = 0; u < 4; ++u) {
                V[u * 4 + 0] = tt[u * 4 + 0] - tt[u * 4 + 2];
                V[u * 4 + 1] = tt[u * 4 + 1] + tt[u * 4 + 2];
                V[u * 4 + 2] = tt[u * 4 + 2] - tt[u * 4 + 1];
                V[u * 4 + 3] = tt[u * 4 + 1] - tt[u * 4 + 3];
            }
#pragma unroll
            for (int r = 0; r < 16; ++r) {
                __half hv = __float2half_rn(V[r]);
                if (cc == 0) vpack[cp][r] = __halves2half2(hv, hv);
                else         vpack[cp][r] = __halves2half2(__low2half(vpack[cp][r]), hv);
            }
        }
    }
#pragma unroll
    for (int r = 0; r < 16; ++r) {
        uint2 w;
        w.x = *(uint32_t*)&vpack[0][r];
        w.y = *(uint32_t*)&vpack[1][r];
        *(uint2*)(g_V + ((size_t)r * 25088 + T) * 256 + lt * 4) = w;
    }
}

// ---------------------------------------------------------------------------
// Kernel 3: Winograd weight transform  U = G g G^T  (fp32 math, fp16 store)
// ---------------------------------------------------------------------------
__global__ __launch_bounds__(256) void wino_wt(const float* __restrict__ W) {
    int oc = blockIdx.x;
    int ic = threadIdx.x;
    const float* g = W + ((size_t)oc * 256 + ic) * 9;
    float gg[9];
#pragma unroll
    for (int i = 0; i < 9; ++i) gg[i] = g[i];
    float tt[12];
#pragma unroll
    for (int j = 0; j < 3; ++j) {
        tt[0 * 3 + j] = gg[0 * 3 + j];
        tt[1 * 3 + j] = 0.5f * (gg[0 * 3 + j] + gg[1 * 3 + j] + gg[2 * 3 + j]);
        tt[2 * 3 + j] = 0.5f * (gg[0 * 3 + j] - gg[1 * 3 + j] + gg[2 * 3 + j]);
        tt[3 * 3 + j] = gg[2 * 3 + j];
    }
#pragma unroll
    for (int u = 0; u < 4; ++u) {
        float U0 = tt[u * 3 + 0];
        float U1 = 0.5f * (tt[u * 3 + 0] + tt[u * 3 + 1] + tt[u * 3 + 2]);
        float U2 = 0.5f * (tt[u * 3 + 0] - tt[u * 3 + 1] + tt[u * 3 + 2]);
        float U3 = tt[u * 3 + 2];
        g_U[(size_t)(u * 4 + 0) * 65536 + oc * 256 + ic] = __float2half_rn(U0);
        g_U[(size_t)(u * 4 + 1) * 65536 + oc * 256 + ic] = __float2half_rn(U1);
        g_U[(size_t)(u * 4 + 2) * 65536 + oc * 256 + ic] = __float2half_rn(U2);
        g_U[(size_t)(u * 4 + 3) * 65536 + oc * 256 + ic] = __float2half_rn(U3);
    }
}

// ---------------------------------------------------------------------------
// Kernel 4: pure GEMM per r (R11 architecture) with BIGGER CTA tile.
// Grid (2 ocb, 196 tb, 16 r) = 6272 CTAs. CTA: 128 tiles x 128 oc, 256 thr,
// 8 warps = 4(m) x 2(n), warp tile 32 tiles x 64 oc = 16 MMA chains.
// K = 256 in 4 chunks of 64; per chunk loads 36KB for 1.05M MACs (1.5x AI
// of R11). 3-stage cp.async ring (110.6KB) -> 2 CTAs/SM. Frags
// single-buffered (saves regs; ptxas pipelines the unrolled loop).
// ---------------------------------------------------------------------------
#define GA_BYTES   (128 * 144)               // 18432
#define GB_BYTES   (128 * 144)               // 18432
#define GSTAGE     (GA_BYTES + GB_BYTES)     // 36864
#define GG_SMEM    (3 * GSTAGE)              // 110592 -> 2 CTAs/SM

#define LDSM4(r0, r1, r2, r3, addr)                                            \
    asm volatile("ldmatrix.sync.aligned.m8n8.x4.shared.b16 {%0,%1,%2,%3}, [%4];" \
                 : "=r"(r0), "=r"(r1), "=r"(r2), "=r"(r3) : "r"(addr))

__global__ __launch_bounds__(256, 2) void wino_gemm2(void) {
    extern __shared__ __half sm[];
    const int t      = threadIdx.x;
    const int lane   = t & 31;
    const int warp   = t >> 5;
    const int warp_m = warp >> 1;   // 0..3 -> 32-tile group
    const int warp_n = warp & 1;    // 0..1 -> 64-oc group
    const int g      = lane >> 2;
    const int t4     = lane & 3;

    const int OB = blockIdx.x * 128;    // oc block
    const int TB = blockIdx.y * 128;    // tile block
    const int r  = blockIdx.z;          // Winograd frequency index

    uint32_t sbase = (uint32_t)__cvta_generic_to_shared(sm);

    // cp.async geometry: 4 A units + 4 B units per thread
    const int row0 = t >> 3;            // 0..31
    const int u0   = t & 7;

    // ldmatrix lane offsets
    const int arow = (lane & 7) + (((lane >> 3) & 1) << 3);
    const int acol = (lane >> 4) << 3;
    const int brow = (lane & 7) + ((lane >> 4) << 3);
    const int bcol = ((lane >> 3) & 1) << 3;
    uint32_t aoff[2], boff[4];
#pragma unroll
    for (int mt = 0; mt < 2; ++mt)
        aoff[mt] = (uint32_t)(((warp_m * 32 + mt * 16 + arow) * 72 + acol) * 2);
#pragma unroll
    for (int j = 0; j < 4; ++j)
        boff[j] = (uint32_t)(GA_BYTES + ((warp_n * 64 + j * 16 + brow) * 72 + bcol) * 2);

    float acc[16][4];
#pragma unroll
    for (int e = 0; e < 16; ++e)
#pragma unroll
        for (int k = 0; k < 4; ++k) acc[e][k] = 0.0f;

    const __half* Vb = g_V + ((size_t)(r * 25088 + TB)) * 256;
    const __half* Ub = g_U + ((size_t)(r * 256 + OB)) * 256;

    auto issue = [&](int kc, int st) {
        uint32_t abase = sbase + (uint32_t)(st * GSTAGE);
        const __half* Vp = Vb + kc * 64 + u0 * 8;
        const __half* Up = Ub + kc * 64 + u0 * 8;
#pragma unroll
        for (int j = 0; j < 4; ++j) {
            int row = row0 + j * 32;
            uint32_t sa = abase + (uint32_t)(row * 144 + u0 * 16);
            asm volatile("cp.async.cg.shared.global [%0], [%1], 16;\n"
                         :: "r"(sa), "l"(Vp + (size_t)row * 256));
        }
#pragma unroll
        for (int j = 0; j < 4; ++j) {
            int row = row0 + j * 32;
            uint32_t sa = abase + (uint32_t)(GA_BYTES + row * 144 + u0 * 16);
            asm volatile("cp.async.cg.shared.global [%0], [%1], 16;\n"
                         :: "r"(sa), "l"(Up + (size_t)row * 256));
        }
        asm volatile("cp.async.commit_group;\n");
    };

    issue(0, 0);
    issue(1, 1);

#pragma unroll
    for (int q = 0; q < 4; ++q) {
        if (q < 3) asm volatile("cp.async.wait_group 1;\n" ::: "memory");
        else       asm volatile("cp.async.wait_group 0;\n" ::: "memory");
        __syncthreads();
        // stage (q-1)%3 is free after this barrier
        if (q + 2 < 4) issue(q + 2, (q + 2) % 3);

        uint32_t abase = sbase + (uint32_t)((q % 3) * GSTAGE);

#pragma unroll
        for (int ks = 0; ks < 4; ++ks) {
            uint32_t ko = (uint32_t)(ks * 32);
            uint32_t a[8], b[16];
            LDSM4(a[0], a[1], a[2], a[3], abase + aoff[0] + ko);
            LDSM4(a[4], a[5], a[6], a[7], abase + aoff[1] + ko);
            LDSM4(b[0],  b[1],  b[2],  b[3],  abase + boff[0] + ko);
            LDSM4(b[4],  b[5],  b[6],  b[7],  abase + boff[1] + ko);
            LDSM4(b[8],  b[9],  b[10], b[11], abase + boff[2] + ko);
            LDSM4(b[12], b[13], b[14], b[15], abase + boff[3] + ko);
#pragma unroll
            for (int mt = 0; mt < 2; ++mt)
#pragma unroll
                for (int nt = 0; nt < 8; ++nt) {
                    int e  = mt * 8 + nt;
                    int bj = (nt >> 1) * 4 + (nt & 1) * 2;
                    asm volatile(
                        "mma.sync.aligned.m16n8k16.row.col.f32.f16.f16.f32 "
                        "{%0,%1,%2,%3}, {%4,%5,%6,%7}, {%8,%9}, {%0,%1,%2,%3};\n"
                        : "+f"(acc[e][0]), "+f"(acc[e][1]),
                          "+f"(acc[e][2]), "+f"(acc[e][3])
                        : "r"(a[mt * 4]), "r"(a[mt * 4 + 1]),
                          "r"(a[mt * 4 + 2]), "r"(a[mt * 4 + 3]),
                          "r"(b[bj]), "r"(b[bj + 1]));
                }
        }
    }

    // Epilogue: regs r0:(tile g, oc) r1:(g, oc+1) r2:(g+8, oc) r3:(g+8, oc+1)
    // -> half2(oc, oc+1) at g_M2[r][ocp][tile]
#pragma unroll
    for (int mt = 0; mt < 2; ++mt)
#pragma unroll
        for (int nt = 0; nt < 8; ++nt) {
            int e   = mt * 8 + nt;
            int T0  = TB + warp_m * 32 + mt * 16 + g;
            int ocp = (OB >> 1) + warp_n * 32 + nt * 4 + t4;   // GLOBAL oc/2
            size_t idx = ((size_t)r * 128 + ocp) * 25088 + T0;
            __half2 h0 = __floats2half2_rn(acc[e][0], acc[e][1]);
            __half2 h1 = __floats2half2_rn(acc[e][2], acc[e][3]);
            g_M2[idx]     = *(uint32_t*)&h0;
            g_M2[idx + 8] = *(uint32_t*)&h1;
        }
}

// ---------------------------------------------------------------------------
// Kernel 5: output transform  Y = A^T M A + bias  (streaming).
// A^T = [[1,1,1,0],[0,1,-1,-1]]
// ---------------------------------------------------------------------------
__global__ __launch_bounds__(256) void wino_out(const float* __restrict__ bias,
                                                float* __restrict__ out) {
    const int lane = threadIdx.x & 31;
    const int warp = threadIdx.x >> 5;
    const int ocp  = blockIdx.y * 8 + warp;
    const int T    = blockIdx.x * 32 + lane;

    const int n   = T / 784;
    const int rem = T - n * 784;
    const int ty  = rem / 28;
    const int tx  = rem - ty * 28;

    uint32_t mv[16];
#pragma unroll
    for (int r = 0; r < 16; ++r)
        mv[r] = g_M2[((size_t)r * 128 + ocp) * 25088 + T];

    size_t base0 = (size_t)n * (256 * 3136) + ((size_t)ocp * 2) * 3136 +
                   (2 * ty) * 56 + 2 * tx;

#pragma unroll
    for (int c = 0; c < 2; ++c) {
        float m[16];
#pragma unroll
        for (int r = 0; r < 16; ++r) {
            float2 f = __half22float2(*(__half2*)&mv[r]);
            m[r] = c ? f.y : f.x;
        }
        float rt0[4], rt1[4];
#pragma unroll
        for (int uu = 0; uu < 4; ++uu) {
            rt0[uu] = m[uu * 4 + 0] + m[uu * 4 + 1] + m[uu * 4 + 2];
            rt1[uu] = m[uu * 4 + 1] - m[uu * 4 + 2] - m[uu * 4 + 3];
        }
        float y00 = rt0[0] + rt0[1] + rt0[2];
        float y01 = rt1[0] + rt1[1] + rt1[2];
        float y10 = rt0[1] - rt0[2] - rt0[3];
        float y11 = rt1[1] - rt1[2] - rt1[3];

        float bv = __ldg(bias + ocp * 2 + c);
        float* ob = out + base0 + (size_t)c * 3136;
        *(float2*)(ob)      = make_float2(y00 + bv, y01 + bv);
        *(float2*)(ob + 56) = make_float2(y10 + bv, y11 + bv);
    }
}

// ---------------------------------------------------------------------------
// Launcher (graph-capturable: kernel launches only)
// ---------------------------------------------------------------------------
extern "C" void kernel_launch(void* const* d_in, const int* in_sizes, int n_in,
                              void* d_out, int out_size) {
    const float* x    = (const float*)d_in[0];
    const float* W    = (const float*)d_in[1];
    const float* b    = (const float*)d_in[2];
    const float* rmsw = (const float*)d_in[3];
    float* out = (float*)d_out;

    wht_kernel<<<dim3(98, 32), 256>>>(x, rmsw);
    wino_in<<<6272, 256>>>();
    wino_wt<<<256, 256>>>(W);

    cudaFuncSetAttribute(wino_gemm2, cudaFuncAttributeMaxDynamicSharedMemorySize,
                         GG_SMEM);
    wino_gemm2<<<dim3(2, 196, 16), 256, GG_SMEM>>>();

    wino_out<<<dim3(784, 16), 256>>>(b, out);
}